// round 3
// baseline (speedup 1.0000x reference)
#include <cuda_runtime.h>
#include <cuda_bf16.h>
#include <math.h>

typedef unsigned long long ull;

#define B_SZ 4
#define T_SZ 12800
#define M_ROWS (B_SZ*T_SZ)   // 51200

// ---------------- static device scratch (no allocation anywhere) ----------------
__device__ __align__(256) float g_aux[4*128*50];
__device__ __align__(256) float g_up1[4*80*216];
__device__ __align__(256) float g_up2[4*80*1728];
__device__ __align__(256) float g_up3[4*80*13824];
__device__ __align__(256) float g_in0[M_ROWS*128];
__device__ __align__(256) float g_iw[512*128];
__device__ __align__(256) float g_h[M_ROWS*512];
__device__ __align__(256) float g_xp[M_ROWS*1536];
__device__ __align__(256) float g_cat[M_ROWS*544];
__device__ __align__(256) float g_f1[M_ROWS*512];
__device__ __align__(256) float g_f2[M_ROWS*512];
__device__ __align__(256) float g_hst[2][2048];   // [buf][b*512+h]
__device__ unsigned g_arrive;
__device__ unsigned g_release;

// ---------------- f32x2 helpers ----------------
__device__ __forceinline__ ull pack2(float x, float y) {
    ull r; asm("mov.b64 %0, {%1,%2};" : "=l"(r) : "f"(x), "f"(y)); return r;
}
__device__ __forceinline__ float2 unpack2(ull v) {
    float2 f; asm("mov.b64 {%0,%1}, %2;" : "=f"(f.x), "=f"(f.y) : "l"(v)); return f;
}
__device__ __forceinline__ void fma2(ull& d, ull a, ull b) {
    asm("fma.rn.f32x2 %0, %1, %2, %0;" : "+l"(d) : "l"(a), "l"(b));
}
__device__ __forceinline__ unsigned ld_acq(unsigned* p) {
    unsigned v; asm volatile("ld.acquire.gpu.u32 %0, [%1];" : "=r"(v) : "l"(p) : "memory"); return v;
}
__device__ __forceinline__ void st_rel(unsigned* p, unsigned v) {
    asm volatile("st.release.gpu.u32 [%0], %1;" :: "l"(p), "r"(v) : "memory");
}

// ---------------- reset (counters + GRU state) ----------------
__global__ void k_reset() {
    int i = blockIdx.x*blockDim.x + threadIdx.x;
    if (i == 0) { g_arrive = 0u; g_release = 0u; }
    if (i < 4096) ((float*)g_hst)[i] = 0.f;
}

// ---------------- mel resnet: one CTA per (b,l) column ----------------
__global__ void k_resnet(const float* __restrict__ mels, const float* __restrict__ w_in,
                         const float* __restrict__ bn0g, const float* __restrict__ bn0b,
                         const float* __restrict__ rc1, const float* __restrict__ rc2,
                         const float* __restrict__ rbn1g, const float* __restrict__ rbn1b,
                         const float* __restrict__ rbn2g, const float* __restrict__ rbn2b,
                         const float* __restrict__ cw, const float* __restrict__ cb,
                         float* __restrict__ aux) {
    int b = blockIdx.x / 50, l = blockIdx.x % 50;
    int o = threadIdx.x;
    __shared__ float mcol[400];
    __shared__ float xs[128], hs[128];
    const float sc = rsqrtf(1.0f + 1e-5f);

    for (int i = o; i < 400; i += 128) {
        int c = i / 5, k = i - c*5;
        mcol[i] = mels[(b*80 + c)*54 + l + k];
    }
    __syncthreads();

    float acc = 0.f;
    const float* wr = w_in + o*400;
    #pragma unroll 8
    for (int i = 0; i < 400; i++) acc += mcol[i] * __ldg(&wr[i]);
    acc = acc*(bn0g[o]*sc) + bn0b[o];
    xs[o] = fmaxf(acc, 0.f);

    for (int ib = 0; ib < 10; ib++) {
        __syncthreads();
        const float* r1 = rc1 + (ib*128 + o)*128;
        float h1 = 0.f;
        #pragma unroll 8
        for (int c = 0; c < 128; c++) h1 += xs[c] * __ldg(&r1[c]);
        h1 = h1*(rbn1g[ib*128+o]*sc) + rbn1b[ib*128+o];
        hs[o] = fmaxf(h1, 0.f);
        __syncthreads();
        const float* r2 = rc2 + (ib*128 + o)*128;
        float h2 = 0.f;
        #pragma unroll 8
        for (int c = 0; c < 128; c++) h2 += hs[c] * __ldg(&r2[c]);
        h2 = h2*(rbn2g[ib*128+o]*sc) + rbn2b[ib*128+o];
        float xn = h2 + xs[o];
        __syncthreads();
        xs[o] = xn;
    }
    __syncthreads();
    float a = 0.f;
    const float* cwr = cw + o*128;
    #pragma unroll 8
    for (int c = 0; c < 128; c++) a += xs[c] * __ldg(&cwr[c]);
    aux[(b*128 + o)*50 + l] = a + cb[o];
}

// ---------------- upsample stage: repeat-by-s then K-tap cross-correlation, pad s ----
__global__ void k_upstage(const float* __restrict__ in, const float* __restrict__ w,
                          float* __restrict__ out, int L, int s, int K, int total) {
    int i = blockIdx.x*256 + threadIdx.x;
    if (i >= total) return;
    int Ls = L*s;
    int row = i / Ls, o = i - row*Ls;
    float acc = 0.f;
    for (int tap = 0; tap < K; tap++) {
        int p = o + tap - s;
        if (p >= 0 && p < Ls) acc += __ldg(&w[tap]) * __ldg(&in[row*L + p/s]);
    }
    out[i] = acc;
}

// ---------------- build padded input matrix for I-layer (M x 128) ----------------
__global__ void k_prep_in(const float* __restrict__ x, float* __restrict__ out) {
    int i = blockIdx.x*256 + threadIdx.x;
    if (i >= M_ROWS*128) return;
    int m = i >> 7, k = i & 127;
    int b = m / T_SZ, t = m - b*T_SZ;
    float v;
    if (k == 0)        v = x[m];
    else if (k <= 80)  v = g_up3[(b*80 + (k-1))*13824 + 512 + t];
    else if (k <= 112) v = g_aux[(b*128 + (k-81))*50 + t/256];
    else               v = 0.f;
    out[i] = v;
}

__global__ void k_pad_iw(const float* __restrict__ iw, float* __restrict__ o) {
    int i = blockIdx.x*256 + threadIdx.x;
    if (i >= 512*128) return;
    int n = i >> 7, k = i & 127;
    o[i] = (k < 113) ? iw[n*113 + k] : 0.f;
}

// ---------------- concat [h(512) | aux slice(32)] -> (M x 544) ----------------
__global__ void k_cat(const float* __restrict__ h, int aoff, float* __restrict__ out) {
    int i = blockIdx.x*256 + threadIdx.x;
    if (i >= M_ROWS*544) return;
    int m = i / 544, j = i - m*544;
    int b = m / T_SZ, t = m - b*T_SZ;
    out[i] = (j < 512) ? h[m*512 + j]
                       : g_aux[(b*128 + aoff + (j-512))*50 + t/256];
}

// ---------------- GEMM: C[m][n] = A[m,:K] . B[n,:K] + bias[n], optional relu ------
// tiles 128x128, bk=16, 256 threads, 8x8 per thread via f32x2
__global__ void __launch_bounds__(256) k_gemm(
        const float* __restrict__ A, const float* __restrict__ B,
        const float* __restrict__ bias, float* __restrict__ C,
        int N, int K, int relu) {
    __shared__ float As[16][132];
    __shared__ float Bs[16][132];
    int tid = threadIdx.x;
    int m0 = blockIdx.y*128, n0 = blockIdx.x*128;
    int tx = tid & 15, ty = tid >> 4;

    ull acc[8][4];
    #pragma unroll
    for (int i = 0; i < 8; i++)
        #pragma unroll
        for (int j = 0; j < 4; j++) acc[i][j] = 0ull;

    for (int kb = 0; kb < K; kb += 16) {
        #pragma unroll
        for (int i = tid; i < 512; i += 256) {
            int row = i >> 2, kq = (i & 3) * 4;
            float4 va = *(const float4*)&A[(size_t)(m0+row)*K + kb + kq];
            As[kq+0][row] = va.x; As[kq+1][row] = va.y;
            As[kq+2][row] = va.z; As[kq+3][row] = va.w;
            float4 vb = *(const float4*)&B[(size_t)(n0+row)*K + kb + kq];
            Bs[kq+0][row] = vb.x; Bs[kq+1][row] = vb.y;
            Bs[kq+2][row] = vb.z; Bs[kq+3][row] = vb.w;
        }
        __syncthreads();
        #pragma unroll
        for (int kk = 0; kk < 16; kk++) {
            float a[8];
            *(float4*)&a[0] = *(const float4*)&As[kk][ty*8];
            *(float4*)&a[4] = *(const float4*)&As[kk][ty*8+4];
            const ull* bp = (const ull*)&Bs[kk][tx*8];
            ull b2[4];
            #pragma unroll
            for (int j = 0; j < 4; j++) b2[j] = bp[j];
            #pragma unroll
            for (int i = 0; i < 8; i++) {
                ull ad = pack2(a[i], a[i]);
                #pragma unroll
                for (int j = 0; j < 4; j++) fma2(acc[i][j], ad, b2[j]);
            }
        }
        __syncthreads();
    }

    #pragma unroll
    for (int i = 0; i < 8; i++) {
        int m = m0 + ty*8 + i;
        float* cp = &C[(size_t)m*N + n0 + tx*8];
        #pragma unroll
        for (int j = 0; j < 4; j++) {
            float2 v = unpack2(acc[i][j]);
            float2 bb = *(const float2*)&bias[n0 + tx*8 + 2*j];
            v.x += bb.x; v.y += bb.y;
            if (relu) { v.x = fmaxf(v.x, 0.f); v.y = fmaxf(v.y, 0.f); }
            *(float2*)&cp[2*j] = v;
        }
    }
}

// ---------------- persistent GRU: 128 CTAs x 128 threads, 4 h-indices per CTA -----
// warp w of CTA c owns h-index c*4+w: computes gh_r/gh_z/gh_n (all 4 batches),
// lanes 0..3 do the gate math for batch=lane. Grid barrier per step.
__global__ void __launch_bounds__(128,1) k_gru(
        const float* __restrict__ whh, const float* __restrict__ bhh,
        const float* __restrict__ xp, float* __restrict__ hio) {
    const int lane = threadIdx.x & 31;
    const int hidx = blockIdx.x*4 + (threadIdx.x >> 5);
    const int tid = threadIdx.x;

    const float* w0 = whh + (size_t)hidx*512;
    const float* w1 = whh + (size_t)(512 + hidx)*512;
    const float* w2 = whh + (size_t)(1024 + hidx)*512;
    const float b_r = bhh[hidx], b_z = bhh[512+hidx], b_n = bhh[1024+hidx];

    float hprev = 0.f;   // lanes 0..3: state for batch=lane

    for (int t = 0; t < T_SZ; t++) {
        const float* hin = g_hst[t & 1];

        ull acc[3][4];
        #pragma unroll
        for (int g = 0; g < 3; g++)
            #pragma unroll
            for (int b = 0; b < 4; b++) acc[g][b] = 0ull;

        #pragma unroll
        for (int j = 0; j < 4; j++) {
            ull hb[4][2];
            #pragma unroll
            for (int b = 0; b < 4; b++) {
                float4 v = __ldcg((const float4*)(hin + b*512 + lane*4 + j*128));
                hb[b][0] = pack2(v.x, v.y);
                hb[b][1] = pack2(v.z, v.w);
            }
            #pragma unroll
            for (int g = 0; g < 3; g++) {
                const float* wg = (g == 0) ? w0 : ((g == 1) ? w1 : w2);
                float4 wv = __ldg((const float4*)(wg + lane*4 + j*128));
                ull wl = pack2(wv.x, wv.y), wh = pack2(wv.z, wv.w);
                #pragma unroll
                for (int b = 0; b < 4; b++) {
                    fma2(acc[g][b], wl, hb[b][0]);
                    fma2(acc[g][b], wh, hb[b][1]);
                }
            }
        }

        float p[12];
        #pragma unroll
        for (int g = 0; g < 3; g++)
            #pragma unroll
            for (int b = 0; b < 4; b++) {
                float2 f = unpack2(acc[g][b]);
                p[g*4+b] = f.x + f.y;
            }
        #pragma unroll
        for (int q = 0; q < 12; q++)
            #pragma unroll
            for (int off = 16; off > 0; off >>= 1)
                p[q] += __shfl_xor_sync(0xffffffffu, p[q], off);

        if (lane < 4) {
            int b = lane;
            int xbase = (b*T_SZ + t)*1536 + hidx;
            float xr = __ldg(&xp[xbase]);
            float xz = __ldg(&xp[xbase + 512]);
            float xn = __ldg(&xp[xbase + 1024]);
            float r = 1.f / (1.f + __expf(-(xr + p[0+b] + b_r)));
            float z = 1.f / (1.f + __expf(-(xz + p[4+b] + b_z)));
            float n = tanhf(xn + r * (p[8+b] + b_n));
            float hn = (1.f - z)*n + z*hprev;
            hprev = hn;
            g_hst[(t+1) & 1][b*512 + hidx] = hn;
            int om = (b*T_SZ + t)*512 + hidx;
            hio[om] += hn;
        }

        __syncthreads();
        if (tid == 0) {
            __threadfence();
            unsigned a = atomicAdd(&g_arrive, 1u);
            unsigned target = (unsigned)(t+1)*128u;
            if (a == target - 1u) {
                st_rel(&g_release, (unsigned)(t+1));
            } else {
                while (ld_acq(&g_release) < (unsigned)(t+1)) {}
            }
        }
        __syncthreads();
    }
}

// ---------------- host ----------------
static float* sym_addr(const void* s) {
    void* p = nullptr;
    cudaGetSymbolAddress(&p, s);
    return (float*)p;
}

extern "C" void kernel_launch(void* const* d_in, const int* in_sizes, int n_in,
                              void* d_out, int out_size) {
    const float* x        = (const float*)d_in[0];
    const float* mels     = (const float*)d_in[1];
    const float* conv_in_w= (const float*)d_in[2];
    const float* bn0_g    = (const float*)d_in[3];
    const float* bn0_b    = (const float*)d_in[4];
    const float* res_c1   = (const float*)d_in[5];
    const float* res_c2   = (const float*)d_in[6];
    const float* rbn1_g   = (const float*)d_in[7];
    const float* rbn1_b   = (const float*)d_in[8];
    const float* rbn2_g   = (const float*)d_in[9];
    const float* rbn2_b   = (const float*)d_in[10];
    const float* conv_ow  = (const float*)d_in[11];
    const float* conv_ob  = (const float*)d_in[12];
    const float* up_w0    = (const float*)d_in[13];
    const float* up_w1    = (const float*)d_in[14];
    const float* up_w2    = (const float*)d_in[15];
    const float* I_w      = (const float*)d_in[16];
    const float* I_b      = (const float*)d_in[17];
    const float* r1_wih   = (const float*)d_in[18];
    const float* r1_whh   = (const float*)d_in[19];
    const float* r1_bih   = (const float*)d_in[20];
    const float* r1_bhh   = (const float*)d_in[21];
    const float* r2_wih   = (const float*)d_in[22];
    const float* r2_whh   = (const float*)d_in[23];
    const float* r2_bih   = (const float*)d_in[24];
    const float* r2_bhh   = (const float*)d_in[25];
    const float* fc1_w    = (const float*)d_in[26];
    const float* fc1_b    = (const float*)d_in[27];
    const float* fc2_w    = (const float*)d_in[28];
    const float* fc2_b    = (const float*)d_in[29];
    const float* fc3_w    = (const float*)d_in[30];
    const float* fc3_b    = (const float*)d_in[31];
    float* out = (float*)d_out;

    float* p_aux = sym_addr(g_aux);
    float* p_up1 = sym_addr(g_up1);
    float* p_up2 = sym_addr(g_up2);
    float* p_up3 = sym_addr(g_up3);
    float* p_in0 = sym_addr(g_in0);
    float* p_iw  = sym_addr(g_iw);
    float* p_h   = sym_addr(g_h);
    float* p_xp  = sym_addr(g_xp);
    float* p_cat = sym_addr(g_cat);
    float* p_f1  = sym_addr(g_f1);
    float* p_f2  = sym_addr(g_f2);

    // 1. aux (mel resnet) and upsample chain
    k_resnet<<<200, 128>>>(mels, conv_in_w, bn0_g, bn0_b, res_c1, res_c2,
                           rbn1_g, rbn1_b, rbn2_g, rbn2_b, conv_ow, conv_ob, p_aux);
    k_upstage<<<(4*80*216 + 255)/256, 256>>>(mels, up_w0, p_up1, 54, 4, 9, 4*80*216);
    k_upstage<<<(4*80*1728 + 255)/256, 256>>>(p_up1, up_w1, p_up2, 216, 8, 17, 4*80*1728);
    k_upstage<<<(4*80*13824 + 255)/256, 256>>>(p_up2, up_w2, p_up3, 1728, 8, 17, 4*80*13824);

    // 2. I layer: h0 = [x | m_up | a1] @ I_w.T + I_b
    k_pad_iw<<<(512*128 + 255)/256, 256>>>(I_w, p_iw);
    k_prep_in<<<(M_ROWS*128)/256, 256>>>(x, p_in0);
    k_gemm<<<dim3(4, 400), 256>>>(p_in0, p_iw, I_b, p_h, 512, 128, 0);

    // 3. GRU1: xp1 then persistent recurrence (h += ys)
    k_gemm<<<dim3(12, 400), 256>>>(p_h, r1_wih, r1_bih, p_xp, 1536, 512, 0);
    k_reset<<<16, 256>>>();
    k_gru<<<128, 128>>>(r1_whh, r1_bhh, p_xp, p_h);

    // 4. GRU2: cat(h, a2) -> xp2 -> recurrence
    k_cat<<<(M_ROWS*544 + 255)/256, 256>>>(p_h, 32, p_cat);
    k_gemm<<<dim3(12, 400), 256>>>(p_cat, r2_wih, r2_bih, p_xp, 1536, 544, 0);
    k_reset<<<16, 256>>>();
    k_gru<<<128, 128>>>(r2_whh, r2_bhh, p_xp, p_h);

    // 5. fc1 / fc2 / fc3
    k_cat<<<(M_ROWS*544 + 255)/256, 256>>>(p_h, 64, p_cat);
    k_gemm<<<dim3(4, 400), 256>>>(p_cat, fc1_w, fc1_b, p_f1, 512, 544, 1);
    k_cat<<<(M_ROWS*544 + 255)/256, 256>>>(p_f1, 96, p_cat);
    k_gemm<<<dim3(4, 400), 256>>>(p_cat, fc2_w, fc2_b, p_f2, 512, 544, 1);
    k_gemm<<<dim3(8, 400), 256>>>(p_f2, fc3_w, fc3_b, out, 1024, 512, 0);
}

// round 4
// speedup vs baseline: 1.5542x; 1.5542x over previous
#include <cuda_runtime.h>
#include <cuda_bf16.h>
#include <math.h>

typedef unsigned long long ull;

#define B_SZ 4
#define T_SZ 12800
#define M_ROWS (B_SZ*T_SZ)   // 51200

// ---------------- static device scratch (no allocation anywhere) ----------------
__device__ __align__(256) float g_aux[4*128*50];
__device__ __align__(256) float g_up1[4*80*216];
__device__ __align__(256) float g_up2[4*80*1728];
__device__ __align__(256) float g_up3[4*80*13824];
__device__ __align__(256) float g_in0[M_ROWS*128];
__device__ __align__(256) float g_iw[512*128];
__device__ __align__(256) float g_h[M_ROWS*512];
__device__ __align__(256) float g_xp[M_ROWS*1536];
__device__ __align__(256) float g_cat[M_ROWS*544];
__device__ __align__(256) float g_f1[M_ROWS*512];
__device__ __align__(256) float g_f2[M_ROWS*512];
__device__ __align__(256) float g_hst[2][2048];   // [buf][b*512+h]
__device__ unsigned g_arrive;

// ---------------- f32x2 / sync helpers ----------------
__device__ __forceinline__ ull pack2(float x, float y) {
    ull r; asm("mov.b64 %0, {%1,%2};" : "=l"(r) : "f"(x), "f"(y)); return r;
}
__device__ __forceinline__ float2 unpack2(ull v) {
    float2 f; asm("mov.b64 {%0,%1}, %2;" : "=f"(f.x), "=f"(f.y) : "l"(v)); return f;
}
__device__ __forceinline__ void fma2(ull& d, ull a, ull b) {
    asm("fma.rn.f32x2 %0, %1, %2, %0;" : "+l"(d) : "l"(a), "l"(b));
}
__device__ __forceinline__ unsigned ld_acq(unsigned* p) {
    unsigned v; asm volatile("ld.acquire.gpu.u32 %0, [%1];" : "=r"(v) : "l"(p) : "memory"); return v;
}
__device__ __forceinline__ void red_rel_add(unsigned* p, unsigned v) {
    asm volatile("red.release.gpu.global.add.u32 [%0], %1;" :: "l"(p), "r"(v) : "memory");
}

// ---------------- reset (counter + GRU state) ----------------
__global__ void k_reset() {
    int i = blockIdx.x*blockDim.x + threadIdx.x;
    if (i == 0) g_arrive = 0u;
    if (i < 4096) ((float*)g_hst)[i] = 0.f;
}

// ---------------- mel resnet: one CTA per (b,l) column ----------------
__global__ void k_resnet(const float* __restrict__ mels, const float* __restrict__ w_in,
                         const float* __restrict__ bn0g, const float* __restrict__ bn0b,
                         const float* __restrict__ rc1, const float* __restrict__ rc2,
                         const float* __restrict__ rbn1g, const float* __restrict__ rbn1b,
                         const float* __restrict__ rbn2g, const float* __restrict__ rbn2b,
                         const float* __restrict__ cw, const float* __restrict__ cb,
                         float* __restrict__ aux) {
    int b = blockIdx.x / 50, l = blockIdx.x % 50;
    int o = threadIdx.x;
    __shared__ float mcol[400];
    __shared__ float xs[128], hs[128];
    const float sc = rsqrtf(1.0f + 1e-5f);

    for (int i = o; i < 400; i += 128) {
        int c = i / 5, k = i - c*5;
        mcol[i] = mels[(b*80 + c)*54 + l + k];
    }
    __syncthreads();

    float acc = 0.f;
    const float* wr = w_in + o*400;
    #pragma unroll 8
    for (int i = 0; i < 400; i++) acc += mcol[i] * __ldg(&wr[i]);
    acc = acc*(bn0g[o]*sc) + bn0b[o];
    xs[o] = fmaxf(acc, 0.f);

    for (int ib = 0; ib < 10; ib++) {
        __syncthreads();
        const float* r1 = rc1 + (ib*128 + o)*128;
        float h1 = 0.f;
        #pragma unroll 8
        for (int c = 0; c < 128; c++) h1 += xs[c] * __ldg(&r1[c]);
        h1 = h1*(rbn1g[ib*128+o]*sc) + rbn1b[ib*128+o];
        hs[o] = fmaxf(h1, 0.f);
        __syncthreads();
        const float* r2 = rc2 + (ib*128 + o)*128;
        float h2 = 0.f;
        #pragma unroll 8
        for (int c = 0; c < 128; c++) h2 += hs[c] * __ldg(&r2[c]);
        h2 = h2*(rbn2g[ib*128+o]*sc) + rbn2b[ib*128+o];
        float xn = h2 + xs[o];
        __syncthreads();
        xs[o] = xn;
    }
    __syncthreads();
    float a = 0.f;
    const float* cwr = cw + o*128;
    #pragma unroll 8
    for (int c = 0; c < 128; c++) a += xs[c] * __ldg(&cwr[c]);
    aux[(b*128 + o)*50 + l] = a + cb[o];
}

// ---------------- upsample stage ----------------
__global__ void k_upstage(const float* __restrict__ in, const float* __restrict__ w,
                          float* __restrict__ out, int L, int s, int K, int total) {
    int i = blockIdx.x*256 + threadIdx.x;
    if (i >= total) return;
    int Ls = L*s;
    int row = i / Ls, o = i - row*Ls;
    float acc = 0.f;
    for (int tap = 0; tap < K; tap++) {
        int p = o + tap - s;
        if (p >= 0 && p < Ls) acc += __ldg(&w[tap]) * __ldg(&in[row*L + p/s]);
    }
    out[i] = acc;
}

// ---------------- build padded input matrix for I-layer (M x 128) ----------------
__global__ void k_prep_in(const float* __restrict__ x, float* __restrict__ out) {
    int i = blockIdx.x*256 + threadIdx.x;
    if (i >= M_ROWS*128) return;
    int m = i >> 7, k = i & 127;
    int b = m / T_SZ, t = m - b*T_SZ;
    float v;
    if (k == 0)        v = x[m];
    else if (k <= 80)  v = g_up3[(b*80 + (k-1))*13824 + 512 + t];
    else if (k <= 112) v = g_aux[(b*128 + (k-81))*50 + t/256];
    else               v = 0.f;
    out[i] = v;
}

__global__ void k_pad_iw(const float* __restrict__ iw, float* __restrict__ o) {
    int i = blockIdx.x*256 + threadIdx.x;
    if (i >= 512*128) return;
    int n = i >> 7, k = i & 127;
    o[i] = (k < 113) ? iw[n*113 + k] : 0.f;
}

// ---------------- concat [h(512) | aux slice(32)] -> (M x 544) ----------------
__global__ void k_cat(const float* __restrict__ h, int aoff, float* __restrict__ out) {
    int i = blockIdx.x*256 + threadIdx.x;
    if (i >= M_ROWS*544) return;
    int m = i / 544, j = i - m*544;
    int b = m / T_SZ, t = m - b*T_SZ;
    out[i] = (j < 512) ? h[m*512 + j]
                       : g_aux[(b*128 + aoff + (j-512))*50 + t/256];
}

// ---------------- GEMM: C[m][n] = A[m,:K] . B[n,:K] + bias[n], optional relu ------
__global__ void __launch_bounds__(256) k_gemm(
        const float* __restrict__ A, const float* __restrict__ B,
        const float* __restrict__ bias, float* __restrict__ C,
        int N, int K, int relu) {
    __shared__ float As[16][132];
    __shared__ float Bs[16][132];
    int tid = threadIdx.x;
    int m0 = blockIdx.y*128, n0 = blockIdx.x*128;
    int tx = tid & 15, ty = tid >> 4;

    ull acc[8][4];
    #pragma unroll
    for (int i = 0; i < 8; i++)
        #pragma unroll
        for (int j = 0; j < 4; j++) acc[i][j] = 0ull;

    for (int kb = 0; kb < K; kb += 16) {
        #pragma unroll
        for (int i = tid; i < 512; i += 256) {
            int row = i >> 2, kq = (i & 3) * 4;
            float4 va = *(const float4*)&A[(size_t)(m0+row)*K + kb + kq];
            As[kq+0][row] = va.x; As[kq+1][row] = va.y;
            As[kq+2][row] = va.z; As[kq+3][row] = va.w;
            float4 vb = *(const float4*)&B[(size_t)(n0+row)*K + kb + kq];
            Bs[kq+0][row] = vb.x; Bs[kq+1][row] = vb.y;
            Bs[kq+2][row] = vb.z; Bs[kq+3][row] = vb.w;
        }
        __syncthreads();
        #pragma unroll
        for (int kk = 0; kk < 16; kk++) {
            float a[8];
            *(float4*)&a[0] = *(const float4*)&As[kk][ty*8];
            *(float4*)&a[4] = *(const float4*)&As[kk][ty*8+4];
            const ull* bp = (const ull*)&Bs[kk][tx*8];
            ull b2[4];
            #pragma unroll
            for (int j = 0; j < 4; j++) b2[j] = bp[j];
            #pragma unroll
            for (int i = 0; i < 8; i++) {
                ull ad = pack2(a[i], a[i]);
                #pragma unroll
                for (int j = 0; j < 4; j++) fma2(acc[i][j], ad, b2[j]);
            }
        }
        __syncthreads();
    }

    #pragma unroll
    for (int i = 0; i < 8; i++) {
        int m = m0 + ty*8 + i;
        float* cp = &C[(size_t)m*N + n0 + tx*8];
        #pragma unroll
        for (int j = 0; j < 4; j++) {
            float2 v = unpack2(acc[i][j]);
            float2 bb = *(const float2*)&bias[n0 + tx*8 + 2*j];
            v.x += bb.x; v.y += bb.y;
            if (relu) { v.x = fmaxf(v.x, 0.f); v.y = fmaxf(v.y, 0.f); }
            *(float2*)&cp[2*j] = v;
        }
    }
}

// ---------------- persistent GRU: 128 CTAs x 128 threads, 1 h-index per warp -----
// Weights register-resident; xp/residual software-pipelined under the barrier
// wait; single-hop release/acquire barrier (no second __syncthreads).
__global__ void __launch_bounds__(128,1) k_gru(
        const float* __restrict__ whh, const float* __restrict__ bhh,
        const float* __restrict__ xp, float* __restrict__ hio) {
    const int lane = threadIdx.x & 31;
    const int hidx = blockIdx.x*4 + (threadIdx.x >> 5);
    const int tid = threadIdx.x;

    // cache the 3 recurrent weight rows in registers (packed f32x2)
    ull wreg[3][4][2];
    #pragma unroll
    for (int g = 0; g < 3; g++) {
        const float* wg = whh + (size_t)(g*512 + hidx)*512;
        #pragma unroll
        for (int j = 0; j < 4; j++) {
            float4 wv = __ldg((const float4*)(wg + lane*4 + j*128));
            wreg[g][j][0] = pack2(wv.x, wv.y);
            wreg[g][j][1] = pack2(wv.z, wv.w);
        }
    }
    const float b_r = bhh[hidx], b_z = bhh[512+hidx], b_n = bhh[1024+hidx];

    float hprev = 0.f;                 // lanes 0..3: state for batch=lane
    float xr = 0.f, xz = 0.f, xn_in = 0.f, hres = 0.f;
    if (lane < 4) {                    // preload t=0 inputs
        int xb = (lane*T_SZ + 0)*1536 + hidx;
        xr    = __ldg(&xp[xb]);
        xz    = __ldg(&xp[xb + 512]);
        xn_in = __ldg(&xp[xb + 1024]);
        hres  = __ldg(&hio[(lane*T_SZ + 0)*512 + hidx]);
    }

    for (int t = 0; t < T_SZ; t++) {
        const float* hin = g_hst[t & 1];

        ull acc[3][4];
        #pragma unroll
        for (int g = 0; g < 3; g++)
            #pragma unroll
            for (int b = 0; b < 4; b++) acc[g][b] = 0ull;

        #pragma unroll
        for (int j = 0; j < 4; j++) {
            ull hb[4][2];
            #pragma unroll
            for (int b = 0; b < 4; b++) {
                float4 v = __ldcg((const float4*)(hin + b*512 + lane*4 + j*128));
                hb[b][0] = pack2(v.x, v.y);
                hb[b][1] = pack2(v.z, v.w);
            }
            #pragma unroll
            for (int g = 0; g < 3; g++)
                #pragma unroll
                for (int b = 0; b < 4; b++) {
                    fma2(acc[g][b], wreg[g][j][0], hb[b][0]);
                    fma2(acc[g][b], wreg[g][j][1], hb[b][1]);
                }
        }

        float p[12];
        #pragma unroll
        for (int g = 0; g < 3; g++)
            #pragma unroll
            for (int b = 0; b < 4; b++) {
                float2 f = unpack2(acc[g][b]);
                p[g*4+b] = f.x + f.y;
            }
        #pragma unroll
        for (int q = 0; q < 12; q++)
            #pragma unroll
            for (int off = 16; off > 0; off >>= 1)
                p[q] += __shfl_xor_sync(0xffffffffu, p[q], off);

        if (lane < 4) {
            int b = lane;
            float r = 1.f / (1.f + __expf(-(xr + p[0+b] + b_r)));
            float z = 1.f / (1.f + __expf(-(xz + p[4+b] + b_z)));
            float n = tanhf(xn_in + r * (p[8+b] + b_n));
            float hn = (1.f - z)*n + z*hprev;
            hprev = hn;
            g_hst[(t+1) & 1][b*512 + hidx] = hn;
            hio[(b*T_SZ + t)*512 + hidx] = hres + hn;   // residual add (prefetched)
        }

        __syncthreads();                     // CTA's reads+stores for step t done
        if (tid == 0) red_rel_add(&g_arrive, 1u);

        // prefetch next step's inputs UNDER the barrier wait
        float xr2 = 0.f, xz2 = 0.f, xn2 = 0.f, hr2 = 0.f;
        if (lane < 4 && t + 1 < T_SZ) {
            int xb = (lane*T_SZ + t + 1)*1536 + hidx;
            xr2 = __ldg(&xp[xb]);
            xz2 = __ldg(&xp[xb + 512]);
            xn2 = __ldg(&xp[xb + 1024]);
            hr2 = __ldg(&hio[(lane*T_SZ + t + 1)*512 + hidx]);
        }

        // single-hop barrier: every lane acquire-polls the counter (one
        // coalesced request per warp); warps proceed independently.
        unsigned tgt = (unsigned)(t + 1) * 128u;
        while (ld_acq(&g_arrive) < tgt) {}

        xr = xr2; xz = xz2; xn_in = xn2; hres = hr2;
    }
}

// ---------------- host ----------------
static float* sym_addr(const void* s) {
    void* p = nullptr;
    cudaGetSymbolAddress(&p, s);
    return (float*)p;
}

extern "C" void kernel_launch(void* const* d_in, const int* in_sizes, int n_in,
                              void* d_out, int out_size) {
    const float* x        = (const float*)d_in[0];
    const float* mels     = (const float*)d_in[1];
    const float* conv_in_w= (const float*)d_in[2];
    const float* bn0_g    = (const float*)d_in[3];
    const float* bn0_b    = (const float*)d_in[4];
    const float* res_c1   = (const float*)d_in[5];
    const float* res_c2   = (const float*)d_in[6];
    const float* rbn1_g   = (const float*)d_in[7];
    const float* rbn1_b   = (const float*)d_in[8];
    const float* rbn2_g   = (const float*)d_in[9];
    const float* rbn2_b   = (const float*)d_in[10];
    const float* conv_ow  = (const float*)d_in[11];
    const float* conv_ob  = (const float*)d_in[12];
    const float* up_w0    = (const float*)d_in[13];
    const float* up_w1    = (const float*)d_in[14];
    const float* up_w2    = (const float*)d_in[15];
    const float* I_w      = (const float*)d_in[16];
    const float* I_b      = (const float*)d_in[17];
    const float* r1_wih   = (const float*)d_in[18];
    const float* r1_whh   = (const float*)d_in[19];
    const float* r1_bih   = (const float*)d_in[20];
    const float* r1_bhh   = (const float*)d_in[21];
    const float* r2_wih   = (const float*)d_in[22];
    const float* r2_whh   = (const float*)d_in[23];
    const float* r2_bih   = (const float*)d_in[24];
    const float* r2_bhh   = (const float*)d_in[25];
    const float* fc1_w    = (const float*)d_in[26];
    const float* fc1_b    = (const float*)d_in[27];
    const float* fc2_w    = (const float*)d_in[28];
    const float* fc2_b    = (const float*)d_in[29];
    const float* fc3_w    = (const float*)d_in[30];
    const float* fc3_b    = (const float*)d_in[31];
    float* out = (float*)d_out;

    float* p_aux = sym_addr(g_aux);
    float* p_up1 = sym_addr(g_up1);
    float* p_up2 = sym_addr(g_up2);
    float* p_up3 = sym_addr(g_up3);
    float* p_in0 = sym_addr(g_in0);
    float* p_iw  = sym_addr(g_iw);
    float* p_h   = sym_addr(g_h);
    float* p_xp  = sym_addr(g_xp);
    float* p_cat = sym_addr(g_cat);
    float* p_f1  = sym_addr(g_f1);
    float* p_f2  = sym_addr(g_f2);

    // 1. aux (mel resnet) and upsample chain
    k_resnet<<<200, 128>>>(mels, conv_in_w, bn0_g, bn0_b, res_c1, res_c2,
                           rbn1_g, rbn1_b, rbn2_g, rbn2_b, conv_ow, conv_ob, p_aux);
    k_upstage<<<(4*80*216 + 255)/256, 256>>>(mels, up_w0, p_up1, 54, 4, 9, 4*80*216);
    k_upstage<<<(4*80*1728 + 255)/256, 256>>>(p_up1, up_w1, p_up2, 216, 8, 17, 4*80*1728);
    k_upstage<<<(4*80*13824 + 255)/256, 256>>>(p_up2, up_w2, p_up3, 1728, 8, 17, 4*80*13824);

    // 2. I layer: h0 = [x | m_up | a1] @ I_w.T + I_b
    k_pad_iw<<<(512*128 + 255)/256, 256>>>(I_w, p_iw);
    k_prep_in<<<(M_ROWS*128)/256, 256>>>(x, p_in0);
    k_gemm<<<dim3(4, 400), 256>>>(p_in0, p_iw, I_b, p_h, 512, 128, 0);

    // 3. GRU1: xp1 then persistent recurrence (h = ys + h)
    k_gemm<<<dim3(12, 400), 256>>>(p_h, r1_wih, r1_bih, p_xp, 1536, 512, 0);
    k_reset<<<16, 256>>>();
    k_gru<<<128, 128>>>(r1_whh, r1_bhh, p_xp, p_h);

    // 4. GRU2: cat(h, a2) -> xp2 -> recurrence
    k_cat<<<(M_ROWS*544 + 255)/256, 256>>>(p_h, 32, p_cat);
    k_gemm<<<dim3(12, 400), 256>>>(p_cat, r2_wih, r2_bih, p_xp, 1536, 544, 0);
    k_reset<<<16, 256>>>();
    k_gru<<<128, 128>>>(r2_whh, r2_bhh, p_xp, p_h);

    // 5. fc1 / fc2 / fc3
    k_cat<<<(M_ROWS*544 + 255)/256, 256>>>(p_h, 64, p_cat);
    k_gemm<<<dim3(4, 400), 256>>>(p_cat, fc1_w, fc1_b, p_f1, 512, 544, 1);
    k_cat<<<(M_ROWS*544 + 255)/256, 256>>>(p_f1, 96, p_cat);
    k_gemm<<<dim3(4, 400), 256>>>(p_cat, fc2_w, fc2_b, p_f2, 512, 544, 1);
    k_gemm<<<dim3(8, 400), 256>>>(p_f2, fc3_w, fc3_b, out, 1024, 512, 0);
}

// round 5
// speedup vs baseline: 1.6724x; 1.0760x over previous
#include <cuda_runtime.h>
#include <cuda_bf16.h>
#include <math.h>

typedef unsigned long long ull;

#define B_SZ 4
#define T_SZ 12800
#define M_ROWS (B_SZ*T_SZ)   // 51200

// ---------------- static device scratch (no allocation anywhere) ----------------
__device__ __align__(256) float g_aux[4*128*50];
__device__ __align__(256) float g_up1[4*80*216];
__device__ __align__(256) float g_up2[4*80*1728];
__device__ __align__(256) float g_up3[4*80*13824];
__device__ __align__(256) float g_in0[M_ROWS*128];
__device__ __align__(256) float g_iw[512*128];
__device__ __align__(256) float g_h[M_ROWS*512];
__device__ __align__(256) float g_xp[M_ROWS*1536];
__device__ __align__(256) float g_cat[M_ROWS*544];
__device__ __align__(256) float g_f1[M_ROWS*512];
__device__ __align__(256) float g_f2[M_ROWS*512];
__device__ __align__(256) float g_hst[2][2048];   // [buf][b*512+h]
__device__ unsigned g_arrive;

// ---------------- f32x2 / sync / math helpers ----------------
__device__ __forceinline__ ull pack2(float x, float y) {
    ull r; asm("mov.b64 %0, {%1,%2};" : "=l"(r) : "f"(x), "f"(y)); return r;
}
__device__ __forceinline__ float2 unpack2(ull v) {
    float2 f; asm("mov.b64 {%0,%1}, %2;" : "=f"(f.x), "=f"(f.y) : "l"(v)); return f;
}
__device__ __forceinline__ void fma2(ull& d, ull a, ull b) {
    asm("fma.rn.f32x2 %0, %1, %2, %0;" : "+l"(d) : "l"(a), "l"(b));
}
__device__ __forceinline__ unsigned ld_acq(unsigned* p) {
    unsigned v; asm volatile("ld.acquire.gpu.u32 %0, [%1];" : "=r"(v) : "l"(p) : "memory"); return v;
}
__device__ __forceinline__ void red_rel_add(unsigned* p, unsigned v) {
    asm volatile("red.release.gpu.global.add.u32 [%0], %1;" :: "l"(p), "r"(v) : "memory");
}
__device__ __forceinline__ float tanh_fast(float x) {
    float y; asm("tanh.approx.f32 %0, %1;" : "=f"(y) : "f"(x)); return y;
}
__device__ __forceinline__ float sig_fast(float x) {
    return fmaf(tanh_fast(0.5f * x), 0.5f, 0.5f);
}

// ---------------- reset (counter + GRU state) ----------------
__global__ void k_reset() {
    int i = blockIdx.x*blockDim.x + threadIdx.x;
    if (i == 0) g_arrive = 0u;
    if (i < 4096) ((float*)g_hst)[i] = 0.f;
}

// ---------------- mel resnet: one CTA per (b,l) column ----------------
__global__ void k_resnet(const float* __restrict__ mels, const float* __restrict__ w_in,
                         const float* __restrict__ bn0g, const float* __restrict__ bn0b,
                         const float* __restrict__ rc1, const float* __restrict__ rc2,
                         const float* __restrict__ rbn1g, const float* __restrict__ rbn1b,
                         const float* __restrict__ rbn2g, const float* __restrict__ rbn2b,
                         const float* __restrict__ cw, const float* __restrict__ cb,
                         float* __restrict__ aux) {
    int b = blockIdx.x / 50, l = blockIdx.x % 50;
    int o = threadIdx.x;
    __shared__ float mcol[400];
    __shared__ float xs[128], hs[128];
    const float sc = rsqrtf(1.0f + 1e-5f);

    for (int i = o; i < 400; i += 128) {
        int c = i / 5, k = i - c*5;
        mcol[i] = mels[(b*80 + c)*54 + l + k];
    }
    __syncthreads();

    float acc = 0.f;
    const float* wr = w_in + o*400;
    #pragma unroll 8
    for (int i = 0; i < 400; i++) acc += mcol[i] * __ldg(&wr[i]);
    acc = acc*(bn0g[o]*sc) + bn0b[o];
    xs[o] = fmaxf(acc, 0.f);

    for (int ib = 0; ib < 10; ib++) {
        __syncthreads();
        const float* r1 = rc1 + (ib*128 + o)*128;
        float h1 = 0.f;
        #pragma unroll 8
        for (int c = 0; c < 128; c++) h1 += xs[c] * __ldg(&r1[c]);
        h1 = h1*(rbn1g[ib*128+o]*sc) + rbn1b[ib*128+o];
        hs[o] = fmaxf(h1, 0.f);
        __syncthreads();
        const float* r2 = rc2 + (ib*128 + o)*128;
        float h2 = 0.f;
        #pragma unroll 8
        for (int c = 0; c < 128; c++) h2 += hs[c] * __ldg(&r2[c]);
        h2 = h2*(rbn2g[ib*128+o]*sc) + rbn2b[ib*128+o];
        float xn = h2 + xs[o];
        __syncthreads();
        xs[o] = xn;
    }
    __syncthreads();
    float a = 0.f;
    const float* cwr = cw + o*128;
    #pragma unroll 8
    for (int c = 0; c < 128; c++) a += xs[c] * __ldg(&cwr[c]);
    aux[(b*128 + o)*50 + l] = a + cb[o];
}

// ---------------- upsample stage ----------------
__global__ void k_upstage(const float* __restrict__ in, const float* __restrict__ w,
                          float* __restrict__ out, int L, int s, int K, int total) {
    int i = blockIdx.x*256 + threadIdx.x;
    if (i >= total) return;
    int Ls = L*s;
    int row = i / Ls, o = i - row*Ls;
    float acc = 0.f;
    for (int tap = 0; tap < K; tap++) {
        int p = o + tap - s;
        if (p >= 0 && p < Ls) acc += __ldg(&w[tap]) * __ldg(&in[row*L + p/s]);
    }
    out[i] = acc;
}

// ---------------- build padded input matrix for I-layer (M x 128) ----------------
__global__ void k_prep_in(const float* __restrict__ x, float* __restrict__ out) {
    int i = blockIdx.x*256 + threadIdx.x;
    if (i >= M_ROWS*128) return;
    int m = i >> 7, k = i & 127;
    int b = m / T_SZ, t = m - b*T_SZ;
    float v;
    if (k == 0)        v = x[m];
    else if (k <= 80)  v = g_up3[(b*80 + (k-1))*13824 + 512 + t];
    else if (k <= 112) v = g_aux[(b*128 + (k-81))*50 + t/256];
    else               v = 0.f;
    out[i] = v;
}

__global__ void k_pad_iw(const float* __restrict__ iw, float* __restrict__ o) {
    int i = blockIdx.x*256 + threadIdx.x;
    if (i >= 512*128) return;
    int n = i >> 7, k = i & 127;
    o[i] = (k < 113) ? iw[n*113 + k] : 0.f;
}

// ---------------- concat [h(512) | aux slice(32)] -> (M x 544) ----------------
__global__ void k_cat(const float* __restrict__ h, int aoff, float* __restrict__ out) {
    int i = blockIdx.x*256 + threadIdx.x;
    if (i >= M_ROWS*544) return;
    int m = i / 544, j = i - m*544;
    int b = m / T_SZ, t = m - b*T_SZ;
    out[i] = (j < 512) ? h[m*512 + j]
                       : g_aux[(b*128 + aoff + (j-512))*50 + t/256];
}

// ---------------- GEMM: C[m][n] = A[m,:K] . B[n,:K] + bias[n], optional relu ------
__global__ void __launch_bounds__(256) k_gemm(
        const float* __restrict__ A, const float* __restrict__ B,
        const float* __restrict__ bias, float* __restrict__ C,
        int N, int K, int relu) {
    __shared__ float As[16][132];
    __shared__ float Bs[16][132];
    int tid = threadIdx.x;
    int m0 = blockIdx.y*128, n0 = blockIdx.x*128;
    int tx = tid & 15, ty = tid >> 4;

    ull acc[8][4];
    #pragma unroll
    for (int i = 0; i < 8; i++)
        #pragma unroll
        for (int j = 0; j < 4; j++) acc[i][j] = 0ull;

    for (int kb = 0; kb < K; kb += 16) {
        #pragma unroll
        for (int i = tid; i < 512; i += 256) {
            int row = i >> 2, kq = (i & 3) * 4;
            float4 va = *(const float4*)&A[(size_t)(m0+row)*K + kb + kq];
            As[kq+0][row] = va.x; As[kq+1][row] = va.y;
            As[kq+2][row] = va.z; As[kq+3][row] = va.w;
            float4 vb = *(const float4*)&B[(size_t)(n0+row)*K + kb + kq];
            Bs[kq+0][row] = vb.x; Bs[kq+1][row] = vb.y;
            Bs[kq+2][row] = vb.z; Bs[kq+3][row] = vb.w;
        }
        __syncthreads();
        #pragma unroll
        for (int kk = 0; kk < 16; kk++) {
            float a[8];
            *(float4*)&a[0] = *(const float4*)&As[kk][ty*8];
            *(float4*)&a[4] = *(const float4*)&As[kk][ty*8+4];
            const ull* bp = (const ull*)&Bs[kk][tx*8];
            ull b2[4];
            #pragma unroll
            for (int j = 0; j < 4; j++) b2[j] = bp[j];
            #pragma unroll
            for (int i = 0; i < 8; i++) {
                ull ad = pack2(a[i], a[i]);
                #pragma unroll
                for (int j = 0; j < 4; j++) fma2(acc[i][j], ad, b2[j]);
            }
        }
        __syncthreads();
    }

    #pragma unroll
    for (int i = 0; i < 8; i++) {
        int m = m0 + ty*8 + i;
        float* cp = &C[(size_t)m*N + n0 + tx*8];
        #pragma unroll
        for (int j = 0; j < 4; j++) {
            float2 v = unpack2(acc[i][j]);
            float2 bb = *(const float2*)&bias[n0 + tx*8 + 2*j];
            v.x += bb.x; v.y += bb.y;
            if (relu) { v.x = fmaxf(v.x, 0.f); v.y = fmaxf(v.y, 0.f); }
            *(float2*)&cp[2*j] = v;
        }
    }
}

// ---------------- persistent GRU: 128 CTAs x 128 threads, 1 h-index per warp -----
// Weights register-resident; xp/residual software-pipelined under the barrier
// wait; grid barrier = red.release by tid0, tid0-only acquire-poll, then
// __syncthreads broadcast (cooperative-groups grid.sync pattern).
__global__ void __launch_bounds__(128,1) k_gru(
        const float* __restrict__ whh, const float* __restrict__ bhh,
        const float* __restrict__ xp, float* __restrict__ hio) {
    const int lane = threadIdx.x & 31;
    const int hidx = blockIdx.x*4 + (threadIdx.x >> 5);
    const int tid = threadIdx.x;

    // cache the 3 recurrent weight rows in registers (packed f32x2)
    ull wreg[3][4][2];
    #pragma unroll
    for (int g = 0; g < 3; g++) {
        const float* wg = whh + (size_t)(g*512 + hidx)*512;
        #pragma unroll
        for (int j = 0; j < 4; j++) {
            float4 wv = __ldg((const float4*)(wg + lane*4 + j*128));
            wreg[g][j][0] = pack2(wv.x, wv.y);
            wreg[g][j][1] = pack2(wv.z, wv.w);
        }
    }
    const float b_r = bhh[hidx], b_z = bhh[512+hidx], b_n = bhh[1024+hidx];

    float hprev = 0.f;                 // lanes 0..3: state for batch=lane
    float xr = 0.f, xz = 0.f, xn_in = 0.f, hres = 0.f;
    if (lane < 4) {                    // preload t=0 inputs
        int xb = (lane*T_SZ + 0)*1536 + hidx;
        xr    = __ldg(&xp[xb]);
        xz    = __ldg(&xp[xb + 512]);
        xn_in = __ldg(&xp[xb + 1024]);
        hres  = __ldg(&hio[(lane*T_SZ + 0)*512 + hidx]);
    }

    for (int t = 0; t < T_SZ; t++) {
        const float* hin = g_hst[t & 1];

        ull acc[3][4];
        #pragma unroll
        for (int g = 0; g < 3; g++)
            #pragma unroll
            for (int b = 0; b < 4; b++) acc[g][b] = 0ull;

        #pragma unroll
        for (int j = 0; j < 4; j++) {
            ull hb[4][2];
            #pragma unroll
            for (int b = 0; b < 4; b++) {
                float4 v = __ldcg((const float4*)(hin + b*512 + lane*4 + j*128));
                hb[b][0] = pack2(v.x, v.y);
                hb[b][1] = pack2(v.z, v.w);
            }
            #pragma unroll
            for (int g = 0; g < 3; g++)
                #pragma unroll
                for (int b = 0; b < 4; b++) {
                    fma2(acc[g][b], wreg[g][j][0], hb[b][0]);
                    fma2(acc[g][b], wreg[g][j][1], hb[b][1]);
                }
        }

        float p[12];
        #pragma unroll
        for (int g = 0; g < 3; g++)
            #pragma unroll
            for (int b = 0; b < 4; b++) {
                float2 f = unpack2(acc[g][b]);
                p[g*4+b] = f.x + f.y;
            }
        #pragma unroll
        for (int q = 0; q < 12; q++)
            #pragma unroll
            for (int off = 16; off > 0; off >>= 1)
                p[q] += __shfl_xor_sync(0xffffffffu, p[q], off);

        float hn = 0.f;
        if (lane < 4) {
            int b = lane;
            float r = sig_fast(xr + p[0+b] + b_r);
            float z = sig_fast(xz + p[4+b] + b_z);
            float n = tanh_fast(xn_in + r * (p[8+b] + b_n));
            hn = (1.f - z)*n + z*hprev;
            hprev = hn;
            g_hst[(t+1) & 1][b*512 + hidx] = hn;
        }

        __syncthreads();                     // all warps' h stores for step t done
        if (tid == 0) red_rel_add(&g_arrive, 1u);

        // residual write off the release-ordered path (never read cross-CTA here)
        if (lane < 4) hio[(lane*T_SZ + t)*512 + hidx] = hres + hn;

        // prefetch next step's inputs UNDER the barrier wait
        float xr2 = 0.f, xz2 = 0.f, xn2 = 0.f, hr2 = 0.f;
        if (lane < 4 && t + 1 < T_SZ) {
            int xb = (lane*T_SZ + t + 1)*1536 + hidx;
            xr2 = __ldg(&xp[xb]);
            xz2 = __ldg(&xp[xb + 512]);
            xn2 = __ldg(&xp[xb + 1024]);
            hr2 = __ldg(&hio[(lane*T_SZ + t + 1)*512 + hidx]);
        }

        if (t + 1 < T_SZ) {
            if (tid == 0) {                  // single poller per CTA
                unsigned tgt = (unsigned)(t + 1) * 128u;
                while (ld_acq(&g_arrive) < tgt) {}
            }
            __syncthreads();                 // broadcast release to the CTA
        }

        xr = xr2; xz = xz2; xn_in = xn2; hres = hr2;
    }
}

// ---------------- host ----------------
static float* sym_addr(const void* s) {
    void* p = nullptr;
    cudaGetSymbolAddress(&p, s);
    return (float*)p;
}

extern "C" void kernel_launch(void* const* d_in, const int* in_sizes, int n_in,
                              void* d_out, int out_size) {
    const float* x        = (const float*)d_in[0];
    const float* mels     = (const float*)d_in[1];
    const float* conv_in_w= (const float*)d_in[2];
    const float* bn0_g    = (const float*)d_in[3];
    const float* bn0_b    = (const float*)d_in[4];
    const float* res_c1   = (const float*)d_in[5];
    const float* res_c2   = (const float*)d_in[6];
    const float* rbn1_g   = (const float*)d_in[7];
    const float* rbn1_b   = (const float*)d_in[8];
    const float* rbn2_g   = (const float*)d_in[9];
    const float* rbn2_b   = (const float*)d_in[10];
    const float* conv_ow  = (const float*)d_in[11];
    const float* conv_ob  = (const float*)d_in[12];
    const float* up_w0    = (const float*)d_in[13];
    const float* up_w1    = (const float*)d_in[14];
    const float* up_w2    = (const float*)d_in[15];
    const float* I_w      = (const float*)d_in[16];
    const float* I_b      = (const float*)d_in[17];
    const float* r1_wih   = (const float*)d_in[18];
    const float* r1_whh   = (const float*)d_in[19];
    const float* r1_bih   = (const float*)d_in[20];
    const float* r1_bhh   = (const float*)d_in[21];
    const float* r2_wih   = (const float*)d_in[22];
    const float* r2_whh   = (const float*)d_in[23];
    const float* r2_bih   = (const float*)d_in[24];
    const float* r2_bhh   = (const float*)d_in[25];
    const float* fc1_w    = (const float*)d_in[26];
    const float* fc1_b    = (const float*)d_in[27];
    const float* fc2_w    = (const float*)d_in[28];
    const float* fc2_b    = (const float*)d_in[29];
    const float* fc3_w    = (const float*)d_in[30];
    const float* fc3_b    = (const float*)d_in[31];
    float* out = (float*)d_out;

    float* p_aux = sym_addr(g_aux);
    float* p_up1 = sym_addr(g_up1);
    float* p_up2 = sym_addr(g_up2);
    float* p_up3 = sym_addr(g_up3);
    float* p_in0 = sym_addr(g_in0);
    float* p_iw  = sym_addr(g_iw);
    float* p_h   = sym_addr(g_h);
    float* p_xp  = sym_addr(g_xp);
    float* p_cat = sym_addr(g_cat);
    float* p_f1  = sym_addr(g_f1);
    float* p_f2  = sym_addr(g_f2);

    // 1. aux (mel resnet) and upsample chain
    k_resnet<<<200, 128>>>(mels, conv_in_w, bn0_g, bn0_b, res_c1, res_c2,
                           rbn1_g, rbn1_b, rbn2_g, rbn2_b, conv_ow, conv_ob, p_aux);
    k_upstage<<<(4*80*216 + 255)/256, 256>>>(mels, up_w0, p_up1, 54, 4, 9, 4*80*216);
    k_upstage<<<(4*80*1728 + 255)/256, 256>>>(p_up1, up_w1, p_up2, 216, 8, 17, 4*80*1728);
    k_upstage<<<(4*80*13824 + 255)/256, 256>>>(p_up2, up_w2, p_up3, 1728, 8, 17, 4*80*13824);

    // 2. I layer: h0 = [x | m_up | a1] @ I_w.T + I_b
    k_pad_iw<<<(512*128 + 255)/256, 256>>>(I_w, p_iw);
    k_prep_in<<<(M_ROWS*128)/256, 256>>>(x, p_in0);
    k_gemm<<<dim3(4, 400), 256>>>(p_in0, p_iw, I_b, p_h, 512, 128, 0);

    // 3. GRU1: xp1 then persistent recurrence (h = ys + h)
    k_gemm<<<dim3(12, 400), 256>>>(p_h, r1_wih, r1_bih, p_xp, 1536, 512, 0);
    k_reset<<<16, 256>>>();
    k_gru<<<128, 128>>>(r1_whh, r1_bhh, p_xp, p_h);

    // 4. GRU2: cat(h, a2) -> xp2 -> recurrence
    k_cat<<<(M_ROWS*544 + 255)/256, 256>>>(p_h, 32, p_cat);
    k_gemm<<<dim3(12, 400), 256>>>(p_cat, r2_wih, r2_bih, p_xp, 1536, 544, 0);
    k_reset<<<16, 256>>>();
    k_gru<<<128, 128>>>(r2_whh, r2_bhh, p_xp, p_h);

    // 5. fc1 / fc2 / fc3
    k_cat<<<(M_ROWS*544 + 255)/256, 256>>>(p_h, 64, p_cat);
    k_gemm<<<dim3(4, 400), 256>>>(p_cat, fc1_w, fc1_b, p_f1, 512, 544, 1);
    k_cat<<<(M_ROWS*544 + 255)/256, 256>>>(p_f1, 96, p_cat);
    k_gemm<<<dim3(4, 400), 256>>>(p_cat, fc2_w, fc2_b, p_f2, 512, 544, 1);
    k_gemm<<<dim3(8, 400), 256>>>(p_f2, fc3_w, fc3_b, out, 1024, 512, 0);
}